// round 13
// baseline (speedup 1.0000x reference)
#include <cuda_runtime.h>

#define IMG    512
#define SW     32          // strip width
#define SH     512         // strip height = full image column strip
#define NCH    16          // chunks per strip (SH/32)
#define BROWS  42          // hh rows (32 new + 10 carry)
#define SROWS  32          // sp/st rows (input buffer)
#define ICOLS  42          // input cols incl. horizontal halo
#define PITCH  44          // input pitch: 16B-aligned rows, conflict-free LDS.128
#define HPITCH 32          // h-pass pitch: conflict-free V reads + aligned STS.128
#define NBLK   512         // 16 col strips * 32 images

#define C1 1.0e-4f
#define C2 9.0e-4f

// Gaussian(sigma=1.5, k=11) weights as literals (match runtime fp32 to ~1e-7;
// loss tolerance is 1e-3). Enables FFMA-imm.
#define WLIT(k) ((k)==0 ? 0.00102838f : (k)==1 ? 0.00759876f : (k)==2 ? 0.03600077f : \
                 (k)==3 ? 0.10936069f : (k)==4 ? 0.21300554f : (k)==5 ? 0.26601172f : \
                 (k)==6 ? 0.21300554f : (k)==7 ? 0.10936069f : (k)==8 ? 0.03600077f : \
                 (k)==9 ? 0.00759876f : 0.00102838f)

__device__ float        g_partial[NBLK];
__device__ unsigned int g_count = 0;

__global__ __launch_bounds__(256, 5) void ssim_strip_kernel(
    const float* __restrict__ pred,
    const float* __restrict__ target,
    float* __restrict__ out)
{
    __shared__ __align__(16) float sp[SROWS][PITCH];
    __shared__ __align__(16) float st[SROWS][PITCH];
    __shared__ __align__(16) float hh[5][BROWS][HPITCH];
    __shared__ float wsum[8];
    __shared__ int   s_last;

    const int tid = threadIdx.x;

    const float* __restrict__ pimg = pred   + (size_t)blockIdx.y * IMG * IMG;
    const float* __restrict__ timg = target + (size_t)blockIdx.y * IMG * IMG;
    const int c0 = blockIdx.x * SW;

    // static decompositions
    const int lrow = tid >> 3;          // 0..31 (load & H-pass row)
    const int lcol = tid & 7;           // 0..7  (load col phase)
    const int hj0  = (tid & 7) * 4;     // H-pass output col base
    const int vj   = tid & 31;          // V-pass col
    const int vi0  = (tid >> 5) * 4;    // V-pass row base

    float local = 0.f;

#define LOAD_ROWS(GR_EXPR, DSTROW, ROWPRED)                                     \
    {                                                                           \
        const int gr = (GR_EXPR);                                               \
        const bool rok = (ROWPRED);                                             \
        const float* __restrict__ prow = pimg + gr * IMG;                       \
        const float* __restrict__ trow = timg + gr * IMG;                       \
        _Pragma("unroll")                                                       \
        for (int s = 0; s < 6; s++) {                                           \
            const int cc = lcol + 8 * s;                                        \
            if (cc < ICOLS) {                                                   \
                const int gc = c0 - 5 + cc;                                     \
                float pv = 0.f, tv = 0.f;                                       \
                if (rok && (unsigned)gc < IMG) {                                \
                    float x = prow[gc];                                         \
                    pv = 1.f / (1.f + __expf(-x));                              \
                    tv = trow[gc];                                              \
                }                                                               \
                sp[(DSTROW)][cc] = pv;                                          \
                st[(DSTROW)][cc] = tv;                                          \
            }                                                                   \
        }                                                                       \
    }

#define HPASS_ROW(SRCROW, DSTROW)                                               \
    {                                                                           \
        const float4* __restrict__ pr4 = (const float4*)&sp[(SRCROW)][hj0];     \
        const float4* __restrict__ tr4 = (const float4*)&st[(SRCROW)][hj0];     \
        float av[16], bv[16];                                                   \
        _Pragma("unroll")                                                       \
        for (int i = 0; i < 4; i++) {                                           \
            const float4 a4 = pr4[i];                                           \
            const float4 b4 = tr4[i];                                           \
            av[4*i+0] = a4.x; av[4*i+1] = a4.y; av[4*i+2] = a4.z; av[4*i+3] = a4.w; \
            bv[4*i+0] = b4.x; bv[4*i+1] = b4.y; bv[4*i+2] = b4.z; bv[4*i+3] = b4.w; \
        }                                                                       \
        float s0[4], s1[4], s2[4], s3[4], s4[4];                                \
        _Pragma("unroll")                                                       \
        for (int u = 0; u < 4; u++) { s0[u]=0.f; s1[u]=0.f; s2[u]=0.f; s3[u]=0.f; s4[u]=0.f; } \
        _Pragma("unroll")                                                       \
        for (int k = 0; k < 14; k++) {                                          \
            const float pa  = av[k];                                            \
            const float pb  = bv[k];                                            \
            const float paa = pa * pa;                                          \
            const float pbb = pb * pb;                                          \
            const float pab = pa * pb;                                          \
            _Pragma("unroll")                                                   \
            for (int u = 0; u < 4; u++) {                                       \
                if (k - u >= 0 && k - u <= 10) {                                \
                    const float wk = WLIT(k - u);                               \
                    s0[u] = fmaf(wk, pa,  s0[u]);                               \
                    s1[u] = fmaf(wk, pb,  s1[u]);                               \
                    s2[u] = fmaf(wk, paa, s2[u]);                               \
                    s3[u] = fmaf(wk, pbb, s3[u]);                               \
                    s4[u] = fmaf(wk, pab, s4[u]);                               \
                }                                                               \
            }                                                                   \
        }                                                                       \
        *(float4*)&hh[0][(DSTROW)][hj0] = make_float4(s0[0], s0[1], s0[2], s0[3]); \
        *(float4*)&hh[1][(DSTROW)][hj0] = make_float4(s1[0], s1[1], s1[2], s1[3]); \
        *(float4*)&hh[2][(DSTROW)][hj0] = make_float4(s2[0], s2[1], s2[2], s2[3]); \
        *(float4*)&hh[3][(DSTROW)][hj0] = make_float4(s3[0], s3[1], s3[2], s3[3]); \
        *(float4*)&hh[4][(DSTROW)][hj0] = make_float4(s4[0], s4[1], s4[2], s4[3]); \
    }

    // =================== prologue =====================
    // P1: input rows -5 .. 26 -> sp[0..31]   (gr may be <0)
    LOAD_ROWS(-5 + lrow, lrow, ((unsigned)gr < IMG));
    __syncthreads();
    HPASS_ROW(lrow, lrow);                 // -> hh rows 0..31
    __syncthreads();
    // P2: input rows 27 .. 36 -> sp[0..9]   (always in range)
    if (lrow < 10) LOAD_ROWS(27 + lrow, lrow, true);
    __syncthreads();
    if (lrow < 10) HPASS_ROW(lrow, 32 + lrow);   // -> hh rows 32..41
    __syncthreads();

    // =================== chunk loop =====================
    for (int ch = 0; ch < NCH; ch++) {
        // ---- V-pass(ch): field-major, register-staged, FFMA-imm ----
        {
            float acc[5][4];
            #pragma unroll
            for (int q = 0; q < 5; q++) {
                float v[14];
                #pragma unroll
                for (int k = 0; k < 14; k++) v[k] = hh[q][vi0 + k][vj];
                #pragma unroll
                for (int u = 0; u < 4; u++) {
                    float a = 0.f;
                    #pragma unroll
                    for (int k = 0; k < 11; k++) a = fmaf(WLIT(k), v[u + k], a);
                    acc[q][u] = a;
                }
            }
            #pragma unroll
            for (int u = 0; u < 4; u++) {
                const float mu1  = acc[0][u];
                const float mu2  = acc[1][u];
                const float mu1s = mu1 * mu1;
                const float mu2s = mu2 * mu2;
                const float mu12 = mu1 * mu2;
                const float sig1  = acc[2][u] - mu1s;
                const float sig2  = acc[3][u] - mu2s;
                const float sig12 = acc[4][u] - mu12;
                const float num = (2.f * mu12 + C1) * (2.f * sig12 + C2);
                const float den = (mu1s + mu2s + C1) * (sig1 + sig2 + C2);
                local += 1.f - __fdividef(num, den);
            }
        }
        __syncthreads();

        if (ch < NCH - 1) {
            // ---- carry hh rows 32..41 -> 0..9 (float4) + load next 32 rows ----
            #pragma unroll
            for (int it = 0; it < 2; it++) {
                const int i = tid + 256 * it;          // 0..399 vec4 tasks
                if (i < 5 * 10 * (SW / 4)) {
                    const int q  = i / 80;
                    const int t  = i - q * 80;
                    const int rr = t >> 3;
                    const int jv = (t & 7) * 4;
                    *(float4*)&hh[q][rr][jv] = *(const float4*)&hh[q][32 + rr][jv];
                }
            }
            // input rows 32*ch + 37 + lrow (can exceed IMG at image bottom)
            LOAD_ROWS(32 * ch + 37 + lrow, lrow, (gr < IMG));
            __syncthreads();

            // ---- H-pass 32 new rows -> hh[10..41] ----
            HPASS_ROW(lrow, 10 + lrow);
            __syncthreads();
        }
    }

    // ---- block reduction -> partial ----
    #pragma unroll
    for (int off = 16; off; off >>= 1)
        local += __shfl_down_sync(0xffffffffu, local, off);
    if ((tid & 31) == 0) wsum[tid >> 5] = local;
    __syncthreads();
    if (tid == 0) {
        float v = 0.f;
        #pragma unroll
        for (int i = 0; i < 8; i++) v += wsum[i];
        int blin = blockIdx.y * 16 + blockIdx.x;
        g_partial[blin] = v;
        __threadfence();
        unsigned old = atomicAdd(&g_count, 1u);
        s_last = (old == NBLK - 1) ? 1 : 0;
    }
    __syncthreads();

    // ---- last block: fixed-order final reduction (bit-deterministic) ----
    if (s_last) {
        __threadfence();
        float s = g_partial[tid] + g_partial[tid + 256];
        #pragma unroll
        for (int off = 16; off; off >>= 1)
            s += __shfl_down_sync(0xffffffffu, s, off);
        if ((tid & 31) == 0) wsum[tid >> 5] = s;
        __syncthreads();
        if (tid == 0) {
            float v = 0.f;
            #pragma unroll
            for (int i = 0; i < 8; i++) v += wsum[i];
            out[0] = v * (1.0f / 8388608.0f);   // / (32*512*512)
            g_count = 0;                        // reset for next graph replay
        }
    }
}

extern "C" void kernel_launch(void* const* d_in, const int* in_sizes, int n_in,
                              void* d_out, int out_size)
{
    const float* pred   = (const float*)d_in[0];
    const float* target = (const float*)d_in[1];
    dim3 grid(16, 32, 1);
    ssim_strip_kernel<<<grid, 256>>>(pred, target, (float*)d_out);
}

// round 14
// speedup vs baseline: 1.1046x; 1.1046x over previous
#include <cuda_runtime.h>

#define IMG    512
#define SW     32
#define SH     256
#define NCH    8
#define BROWS  42          // hh rows (32 new + 10 carry)
#define SROWS  32          // spst rows
#define ICOLS  42
#define PITCH2 42          // spst pitch in float2 (336B rows, 16B-aligned)
#define HPITCH 32          // hh pitch (cols)
#define NBLK   1024        // 16 * 2 * 32

#define C1 1.0e-4f
#define C2 9.0e-4f

// Gaussian(sigma=1.5,k=11) literals (~1e-7 vs runtime fp32; tol 1e-3)
#define WLIT(k) ((k)==0 ? 0.00102838f : (k)==1 ? 0.00759876f : (k)==2 ? 0.03600077f : \
                 (k)==3 ? 0.10936069f : (k)==4 ? 0.21300554f : (k)==5 ? 0.26601172f : \
                 (k)==6 ? 0.21300554f : (k)==7 ? 0.10936069f : (k)==8 ? 0.03600077f : \
                 (k)==9 ? 0.00759876f : 0.00102838f)

typedef unsigned long long ull;

__device__ __forceinline__ ull d_pack2(float lo, float hi) {
    ull r; asm("mov.b64 %0, {%1, %2};" : "=l"(r) : "f"(lo), "f"(hi)); return r;
}
__device__ __forceinline__ void d_unpack2(ull v, float& lo, float& hi) {
    asm("mov.b64 {%0, %1}, %2;" : "=f"(lo), "=f"(hi) : "l"(v));
}
#define FMA2(acc, a, b) asm("fma.rn.f32x2 %0, %1, %2, %0;" : "+l"(acc) : "l"(a), "l"(b))
#define MUL2(d, a, b)   asm("mul.rn.f32x2 %0, %1, %2;"      : "=l"(d)  : "l"(a), "l"(b))

__device__ float        g_partial[NBLK];
__device__ unsigned int g_count = 0;

__global__ __launch_bounds__(256, 4) void ssim_strip_kernel(
    const float* __restrict__ pred,
    const float* __restrict__ target,
    float* __restrict__ out)
{
    __shared__ __align__(16) float2 spst[SROWS][PITCH2];  // (sigmoid(p), t)
    __shared__ __align__(16) float2 hh01[BROWS][HPITCH];  // (blur_h p, blur_h t)
    __shared__ __align__(16) float2 hh23[BROWS][HPITCH];  // (blur_h p^2, blur_h t^2)
    __shared__ __align__(16) float  hh4 [BROWS][HPITCH];  // blur_h p*t
    __shared__ float wsum[8];
    __shared__ int   s_last;

    const int tid = threadIdx.x;

    const float* __restrict__ pimg = pred   + (size_t)blockIdx.z * IMG * IMG;
    const float* __restrict__ timg = target + (size_t)blockIdx.z * IMG * IMG;
    const int c0 = blockIdx.x * SW;
    const int r0 = blockIdx.y * SH;

    // decompositions
    const int lrow = tid >> 3;          // 0..31 load row
    const int lcol = tid & 7;           // 0..7  load col phase
    const int hr2  = tid >> 4;          // 0..15 H-pass row within pass
    const int hc2  = (tid & 15) * 2;    // 0..30 H-pass output col base
    const int vj   = tid & 31;          // V-pass col
    const int vi0  = (tid >> 5) * 4;    // V-pass row base

    // packed weights (hoisted, live in regs)
    ull w2[11];
    #pragma unroll
    for (int k = 0; k < 11; k++) w2[k] = d_pack2(WLIT(k), WLIT(k));

    float local = 0.f;

#define LOAD_ROWS(GR_EXPR, DSTROW, ROWPRED)                                     \
    {                                                                           \
        const int gr = (GR_EXPR);                                               \
        const bool rok = (ROWPRED);                                             \
        const float* __restrict__ prow = pimg + gr * IMG;                       \
        const float* __restrict__ trow = timg + gr * IMG;                       \
        _Pragma("unroll")                                                       \
        for (int s = 0; s < 6; s++) {                                           \
            const int cc = lcol + 8 * s;                                        \
            if (cc < ICOLS) {                                                   \
                const int gc = c0 - 5 + cc;                                     \
                float pv = 0.f, tv = 0.f;                                       \
                if (rok && (unsigned)gc < IMG) {                                \
                    float x = prow[gc];                                         \
                    pv = 1.f / (1.f + __expf(-x));                              \
                    tv = trow[gc];                                              \
                }                                                               \
                spst[(DSTROW)][cc] = make_float2(pv, tv);                       \
            }                                                                   \
        }                                                                       \
    }

#define HP_TAP(K, PA, PB)                                                       \
    {                                                                           \
        const float pa = (PA), pb = (PB);                                       \
        ull ab = d_pack2(pa, pb);                                               \
        ull abab; MUL2(abab, ab, ab);                                           \
        const float pab = pa * pb;                                              \
        if ((K) <= 10) {                                                        \
            FMA2(a01_0, w2[(K)], ab); FMA2(a23_0, w2[(K)], abab);               \
            a4_0 = fmaf(WLIT(K), pab, a4_0);                                    \
        }                                                                       \
        if ((K) >= 1 && (K) <= 11) {                                            \
            FMA2(a01_1, w2[(K)-1], ab); FMA2(a23_1, w2[(K)-1], abab);           \
            a4_1 = fmaf(WLIT((K)-1), pab, a4_1);                                \
        }                                                                       \
    }

#define HPASS2(SRCROW, DSTROW)                                                  \
    {                                                                           \
        ull a01_0 = 0ull, a01_1 = 0ull, a23_0 = 0ull, a23_1 = 0ull;             \
        float a4_0 = 0.f, a4_1 = 0.f;                                           \
        _Pragma("unroll")                                                       \
        for (int kk = 0; kk < 6; kk++) {                                        \
            const float4 qv = *reinterpret_cast<const float4*>(                 \
                                   &spst[(SRCROW)][hc2 + 2 * kk]);              \
            HP_TAP(2 * kk,     qv.x, qv.y);                                     \
            HP_TAP(2 * kk + 1, qv.z, qv.w);                                     \
        }                                                                       \
        *reinterpret_cast<ulonglong2*>(&hh01[(DSTROW)][hc2]) =                  \
            make_ulonglong2(a01_0, a01_1);                                      \
        *reinterpret_cast<ulonglong2*>(&hh23[(DSTROW)][hc2]) =                  \
            make_ulonglong2(a23_0, a23_1);                                      \
        *reinterpret_cast<float2*>(&hh4[(DSTROW)][hc2]) =                       \
            make_float2(a4_0, a4_1);                                            \
    }

    // =================== prologue =====================
    LOAD_ROWS(r0 - 5 + lrow, lrow, ((unsigned)gr < IMG));   // rows -5..26
    __syncthreads();
    HPASS2(hr2,      hr2);          // hh rows 0..15
    HPASS2(hr2 + 16, hr2 + 16);     // hh rows 16..31
    __syncthreads();
    if (lrow < 10) LOAD_ROWS(r0 + 27 + lrow, lrow, true);   // rows 27..36
    __syncthreads();
    if (hr2 < 10) HPASS2(hr2, 32 + hr2);                    // hh rows 32..41
    __syncthreads();

    // =================== chunk loop =====================
    for (int ch = 0; ch < NCH; ch++) {
        // ---- V-pass + SSIM (packed) ----
        {
            ull acc01[4], acc23[4];
            float acc4[4];
            #pragma unroll
            for (int u = 0; u < 4; u++) { acc01[u] = 0ull; acc23[u] = 0ull; acc4[u] = 0.f; }

            #pragma unroll
            for (int k = 0; k < 14; k++) {
                const ull v01 = *reinterpret_cast<const ull*>(&hh01[vi0 + k][vj]);
                const ull v23 = *reinterpret_cast<const ull*>(&hh23[vi0 + k][vj]);
                const float v4 = hh4[vi0 + k][vj];
                #pragma unroll
                for (int u = 0; u < 4; u++) {
                    if (k - u >= 0 && k - u <= 10) {
                        FMA2(acc01[u], w2[k - u], v01);
                        FMA2(acc23[u], w2[k - u], v23);
                        acc4[u] = fmaf(WLIT(k - u), v4, acc4[u]);
                    }
                }
            }

            #pragma unroll
            for (int u = 0; u < 4; u++) {
                float mu1, mu2, bp, bt;
                d_unpack2(acc01[u], mu1, mu2);
                d_unpack2(acc23[u], bp, bt);
                const float mu1s = mu1 * mu1;
                const float mu2s = mu2 * mu2;
                const float mu12 = mu1 * mu2;
                const float sig1  = bp - mu1s;
                const float sig2  = bt - mu2s;
                const float sig12 = acc4[u] - mu12;
                const float num = (2.f * mu12 + C1) * (2.f * sig12 + C2);
                const float den = (mu1s + mu2s + C1) * (sig1 + sig2 + C2);
                local += 1.f - __fdividef(num, den);
            }
        }
        __syncthreads();

        if (ch < NCH - 1) {
            // ---- carry hh rows 32..41 -> 0..9 (float4, contiguous rows) ----
            {
                float4* f01 = reinterpret_cast<float4*>(hh01);  // 16 f4/row
                float4* f23 = reinterpret_cast<float4*>(hh23);
                float4* f4p = reinterpret_cast<float4*>(hh4);   //  8 f4/row
                #pragma unroll
                for (int it = 0; it < 2; it++) {
                    const int i = tid + 256 * it;               // 0..399
                    if (i < 160)      f01[i]       = f01[512 + i];
                    else if (i < 320) f23[i - 160] = f23[512 + (i - 160)];
                    else if (i < 400) f4p[i - 320] = f4p[256 + (i - 320)];
                }
            }
            // ---- load next 32 input rows ----
            LOAD_ROWS(r0 + 32 * ch + 37 + lrow, lrow, (gr < IMG));
            __syncthreads();

            // ---- H-pass 32 new rows -> hh rows 10..41 ----
            HPASS2(hr2,      10 + hr2);
            HPASS2(hr2 + 16, 26 + hr2);
            __syncthreads();
        }
    }

    // ---- block reduction -> partial ----
    #pragma unroll
    for (int off = 16; off; off >>= 1)
        local += __shfl_down_sync(0xffffffffu, local, off);
    if ((tid & 31) == 0) wsum[tid >> 5] = local;
    __syncthreads();
    if (tid == 0) {
        float v = 0.f;
        #pragma unroll
        for (int i = 0; i < 8; i++) v += wsum[i];
        int blin = (blockIdx.z * 2 + blockIdx.y) * 16 + blockIdx.x;
        g_partial[blin] = v;
        __threadfence();
        unsigned old = atomicAdd(&g_count, 1u);
        s_last = (old == NBLK - 1) ? 1 : 0;
    }
    __syncthreads();

    // ---- last block: fixed-order final reduction ----
    if (s_last) {
        __threadfence();
        float s = g_partial[tid] + g_partial[tid + 256]
                + g_partial[tid + 512] + g_partial[tid + 768];
        #pragma unroll
        for (int off = 16; off; off >>= 1)
            s += __shfl_down_sync(0xffffffffu, s, off);
        if ((tid & 31) == 0) wsum[tid >> 5] = s;
        __syncthreads();
        if (tid == 0) {
            float v = 0.f;
            #pragma unroll
            for (int i = 0; i < 8; i++) v += wsum[i];
            out[0] = v * (1.0f / 8388608.0f);   // / (32*512*512)
            g_count = 0;                        // reset for next graph replay
        }
    }
}

extern "C" void kernel_launch(void* const* d_in, const int* in_sizes, int n_in,
                              void* d_out, int out_size)
{
    const float* pred   = (const float*)d_in[0];
    const float* target = (const float*)d_in[1];
    dim3 grid(16, 2, 32);
    ssim_strip_kernel<<<grid, 256>>>(pred, target, (float*)d_out);
}

// round 16
// speedup vs baseline: 1.1132x; 1.0078x over previous
#include <cuda_runtime.h>

#define IMG    512
#define SW     32
#define SH     256
#define NCH    8
#define BROWS  42          // hh rows (32 new + 10 carry)
#define SROWS  32          // spst rows
#define ICOLS  42
#define PITCH2 42          // spst pitch in float2 (336B rows, 16B-aligned)
#define HPITCH 32          // hh pitch (cols)
#define NBLK   1024        // 16 * 2 * 32

#define C1 1.0e-4f
#define C2 9.0e-4f

// Gaussian(sigma=1.5,k=11) literals (~1e-7 vs runtime fp32; tol 1e-3)
#define WLIT(k) ((k)==0 ? 0.00102838f : (k)==1 ? 0.00759876f : (k)==2 ? 0.03600077f : \
                 (k)==3 ? 0.10936069f : (k)==4 ? 0.21300554f : (k)==5 ? 0.26601172f : \
                 (k)==6 ? 0.21300554f : (k)==7 ? 0.10936069f : (k)==8 ? 0.03600077f : \
                 (k)==9 ? 0.00759876f : 0.00102838f)
// symmetric window: w[k] == w[10-k]; only 6 unique packed registers needed
#define W2X(k) ((k) <= 5 ? (k) : 10 - (k))

typedef unsigned long long ull;

__device__ __forceinline__ ull d_pack2(float lo, float hi) {
    ull r; asm("mov.b64 %0, {%1, %2};" : "=l"(r) : "f"(lo), "f"(hi)); return r;
}
__device__ __forceinline__ void d_unpack2(ull v, float& lo, float& hi) {
    asm("mov.b64 {%0, %1}, %2;" : "=f"(lo), "=f"(hi) : "l"(v));
}
#define FMA2(acc, a, b) asm("fma.rn.f32x2 %0, %1, %2, %0;" : "+l"(acc) : "l"(a), "l"(b))
#define MUL2(d, a, b)   asm("mul.rn.f32x2 %0, %1, %2;"      : "=l"(d)  : "l"(a), "l"(b))

__device__ float        g_partial[NBLK];
__device__ unsigned int g_count = 0;

__global__ __launch_bounds__(256, 5) void ssim_strip_kernel(
    const float* __restrict__ pred,
    const float* __restrict__ target,
    float* __restrict__ out)
{
    __shared__ __align__(16) float2 spst[SROWS][PITCH2];  // (sigmoid(p), t)
    __shared__ __align__(16) float2 hh01[BROWS][HPITCH];  // (blur_h p, blur_h t)
    __shared__ __align__(16) float2 hh23[BROWS][HPITCH];  // (blur_h p^2, blur_h t^2)
    __shared__ __align__(16) float  hh4 [BROWS][HPITCH];  // blur_h p*t
    __shared__ float wsum[8];
    __shared__ int   s_last;

    const int tid = threadIdx.x;

    const float* __restrict__ pimg = pred   + (size_t)blockIdx.z * IMG * IMG;
    const float* __restrict__ timg = target + (size_t)blockIdx.z * IMG * IMG;
    const int c0 = blockIdx.x * SW;
    const int r0 = blockIdx.y * SH;

    // decompositions
    const int lrow = tid >> 3;          // 0..31 load row
    const int lcol = tid & 7;           // 0..7  load col phase
    const int hr2  = tid >> 4;          // 0..15 H-pass row within pass
    const int hc2  = (tid & 15) * 2;    // 0..30 H-pass output col base
    const int vj   = tid & 31;          // V-pass col
    const int vi0  = (tid >> 5) * 4;    // V-pass row base

    // packed weights: 6 unique (symmetric window), hoisted into regs
    ull w2[6];
    #pragma unroll
    for (int k = 0; k < 6; k++) w2[k] = d_pack2(WLIT(k), WLIT(k));

    float local = 0.f;

#define LOAD_ROWS(GR_EXPR, DSTROW, ROWPRED)                                     \
    {                                                                           \
        const int gr = (GR_EXPR);                                               \
        const bool rok = (ROWPRED);                                             \
        const float* __restrict__ prow = pimg + gr * IMG;                       \
        const float* __restrict__ trow = timg + gr * IMG;                       \
        _Pragma("unroll")                                                       \
        for (int s = 0; s < 6; s++) {                                           \
            const int cc = lcol + 8 * s;                                        \
            if (cc < ICOLS) {                                                   \
                const int gc = c0 - 5 + cc;                                     \
                float pv = 0.f, tv = 0.f;                                       \
                if (rok && (unsigned)gc < IMG) {                                \
                    float x = prow[gc];                                         \
                    pv = 1.f / (1.f + __expf(-x));                              \
                    tv = trow[gc];                                              \
                }                                                               \
                spst[(DSTROW)][cc] = make_float2(pv, tv);                       \
            }                                                                   \
        }                                                                       \
    }

#define HP_TAP(K, PA, PB)                                                       \
    {                                                                           \
        const float pa = (PA), pb = (PB);                                       \
        ull ab = d_pack2(pa, pb);                                               \
        ull abab; MUL2(abab, ab, ab);                                           \
        const float pab = pa * pb;                                              \
        if ((K) <= 10) {                                                        \
            FMA2(a01_0, w2[W2X(K)], ab); FMA2(a23_0, w2[W2X(K)], abab);         \
            a4_0 = fmaf(WLIT(K), pab, a4_0);                                    \
        }                                                                       \
        if ((K) >= 1 && (K) <= 11) {                                            \
            FMA2(a01_1, w2[W2X((K)-1)], ab); FMA2(a23_1, w2[W2X((K)-1)], abab); \
            a4_1 = fmaf(WLIT((K)-1), pab, a4_1);                                \
        }                                                                       \
    }

#define HPASS2(SRCROW, DSTROW)                                                  \
    {                                                                           \
        ull a01_0 = 0ull, a01_1 = 0ull, a23_0 = 0ull, a23_1 = 0ull;             \
        float a4_0 = 0.f, a4_1 = 0.f;                                           \
        _Pragma("unroll")                                                       \
        for (int kk = 0; kk < 6; kk++) {                                        \
            const float4 qv = *reinterpret_cast<const float4*>(                 \
                                   &spst[(SRCROW)][hc2 + 2 * kk]);              \
            HP_TAP(2 * kk,     qv.x, qv.y);                                     \
            HP_TAP(2 * kk + 1, qv.z, qv.w);                                     \
        }                                                                       \
        *reinterpret_cast<ulonglong2*>(&hh01[(DSTROW)][hc2]) =                  \
            make_ulonglong2(a01_0, a01_1);                                      \
        *reinterpret_cast<ulonglong2*>(&hh23[(DSTROW)][hc2]) =                  \
            make_ulonglong2(a23_0, a23_1);                                      \
        *reinterpret_cast<float2*>(&hh4[(DSTROW)][hc2]) =                       \
            make_float2(a4_0, a4_1);                                            \
    }

    // =================== prologue =====================
    LOAD_ROWS(r0 - 5 + lrow, lrow, ((unsigned)gr < IMG));   // rows -5..26
    __syncthreads();
    HPASS2(hr2,      hr2);          // hh rows 0..15
    HPASS2(hr2 + 16, hr2 + 16);     // hh rows 16..31
    __syncthreads();
    if (lrow < 10) LOAD_ROWS(r0 + 27 + lrow, lrow, true);   // rows 27..36
    __syncthreads();
    if (hr2 < 10) HPASS2(hr2, 32 + hr2);                    // hh rows 32..41
    __syncthreads();

    // =================== chunk loop =====================
    for (int ch = 0; ch < NCH; ch++) {
        // ---- V-pass + SSIM (packed) ----
        {
            ull acc01[4], acc23[4];
            float acc4[4];
            #pragma unroll
            for (int u = 0; u < 4; u++) { acc01[u] = 0ull; acc23[u] = 0ull; acc4[u] = 0.f; }

            #pragma unroll
            for (int k = 0; k < 14; k++) {
                const ull v01 = *reinterpret_cast<const ull*>(&hh01[vi0 + k][vj]);
                const ull v23 = *reinterpret_cast<const ull*>(&hh23[vi0 + k][vj]);
                const float v4 = hh4[vi0 + k][vj];
                #pragma unroll
                for (int u = 0; u < 4; u++) {
                    if (k - u >= 0 && k - u <= 10) {
                        FMA2(acc01[u], w2[W2X(k - u)], v01);
                        FMA2(acc23[u], w2[W2X(k - u)], v23);
                        acc4[u] = fmaf(WLIT(k - u), v4, acc4[u]);
                    }
                }
            }

            #pragma unroll
            for (int u = 0; u < 4; u++) {
                float mu1, mu2, bp, bt;
                d_unpack2(acc01[u], mu1, mu2);
                d_unpack2(acc23[u], bp, bt);
                const float mu1s = mu1 * mu1;
                const float mu2s = mu2 * mu2;
                const float mu12 = mu1 * mu2;
                const float sig1  = bp - mu1s;
                const float sig2  = bt - mu2s;
                const float sig12 = acc4[u] - mu12;
                const float num = (2.f * mu12 + C1) * (2.f * sig12 + C2);
                const float den = (mu1s + mu2s + C1) * (sig1 + sig2 + C2);
                local += 1.f - __fdividef(num, den);
            }
        }
        __syncthreads();

        if (ch < NCH - 1) {
            // ---- carry hh rows 32..41 -> 0..9 (float4, contiguous rows) ----
            {
                float4* f01 = reinterpret_cast<float4*>(hh01);  // 16 f4/row
                float4* f23 = reinterpret_cast<float4*>(hh23);
                float4* f4p = reinterpret_cast<float4*>(hh4);   //  8 f4/row
                #pragma unroll
                for (int it = 0; it < 2; it++) {
                    const int i = tid + 256 * it;               // 0..399
                    if (i < 160)      f01[i]       = f01[512 + i];
                    else if (i < 320) f23[i - 160] = f23[512 + (i - 160)];
                    else if (i < 400) f4p[i - 320] = f4p[256 + (i - 320)];
                }
            }
            // ---- load next 32 input rows ----
            LOAD_ROWS(r0 + 32 * ch + 37 + lrow, lrow, (gr < IMG));
            __syncthreads();

            // ---- H-pass 32 new rows -> hh rows 10..41 ----
            HPASS2(hr2,      10 + hr2);
            HPASS2(hr2 + 16, 26 + hr2);
            __syncthreads();
        }
    }

    // ---- block reduction -> partial ----
    #pragma unroll
    for (int off = 16; off; off >>= 1)
        local += __shfl_down_sync(0xffffffffu, local, off);
    if ((tid & 31) == 0) wsum[tid >> 5] = local;
    __syncthreads();
    if (tid == 0) {
        float v = 0.f;
        #pragma unroll
        for (int i = 0; i < 8; i++) v += wsum[i];
        int blin = (blockIdx.z * 2 + blockIdx.y) * 16 + blockIdx.x;
        g_partial[blin] = v;
        __threadfence();
        unsigned old = atomicAdd(&g_count, 1u);
        s_last = (old == NBLK - 1) ? 1 : 0;
    }
    __syncthreads();

    // ---- last block: fixed-order final reduction ----
    if (s_last) {
        __threadfence();
        float s = g_partial[tid] + g_partial[tid + 256]
                + g_partial[tid + 512] + g_partial[tid + 768];
        #pragma unroll
        for (int off = 16; off; off >>= 1)
            s += __shfl_down_sync(0xffffffffu, s, off);
        if ((tid & 31) == 0) wsum[tid >> 5] = s;
        __syncthreads();
        if (tid == 0) {
            float v = 0.f;
            #pragma unroll
            for (int i = 0; i < 8; i++) v += wsum[i];
            out[0] = v * (1.0f / 8388608.0f);   // / (32*512*512)
            g_count = 0;                        // reset for next graph replay
        }
    }
}

extern "C" void kernel_launch(void* const* d_in, const int* in_sizes, int n_in,
                              void* d_out, int out_size)
{
    const float* pred   = (const float*)d_in[0];
    const float* target = (const float*)d_in[1];
    dim3 grid(16, 2, 32);
    ssim_strip_kernel<<<grid, 256>>>(pred, target, (float*)d_out);
}